// round 16
// baseline (speedup 1.0000x reference)
#include <cuda_runtime.h>
#include <cuda_fp16.h>
#include <cstdint>
#include <cstddef>

// Problem constants
#define B_  2
#define N_  2048
#define D_  1024
#define H_  16
#define EQ_ 3072
#define M_ROWS 4096
#define NQK 2048            // q,k output columns (64 q + 64 k per head)

#define QSCALE (0.125f * 1.4426950408889634f)   // 1/sqrt(64) * log2(e)

// Scratch (no allocations allowed). fp16; contracted dims stored with the
// 16-group permutation: word w (even) holds (j=w, j+1); word w (odd) holds
// (j=w+7, j+8)  -> LDS.64 of words (2t, 2t+1) yields logical (k,k+1,k+8,k+9).
__device__ __half g_x16 [(size_t)M_ROWS * D_];    //  8 MB, x fp16 perm-k
__device__ __half g_wqk [(size_t)NQK * D_];       //  4 MB, Wqk^T rows, q ×QSCALE
__device__ __half g_wv  [(size_t)D_ * D_];        //  2 MB, Wv^T rows
__device__ __half g_wo  [(size_t)D_ * D_];        //  2 MB, Wout^T rows
__device__ __half g_qk  [(size_t)M_ROWS * NQK];   // 16 MB, QK proj out (perm d)
__device__ __half g_vT  [(size_t)D_ * M_ROWS];    //  8 MB, V^T (perm tokens)
__device__ __half g_at16[(size_t)M_ROWS * D_];    //  8 MB, attn out (perm hd)

// ---------------------------------------------------------------------------
// Helpers
// ---------------------------------------------------------------------------
__device__ __forceinline__ uint32_t smem_u32(const void* p) {
    uint32_t a;
    asm("{ .reg .u64 t; cvta.to.shared.u64 t, %1; cvt.u32.u64 %0, t; }"
        : "=r"(a) : "l"(p));
    return a;
}

__device__ __forceinline__ uint32_t packh2(float lo, float hi) {
    __half2 h = __floats2half2_rn(lo, hi);
    return *(uint32_t*)&h;
}

__device__ __forceinline__ float2 h2f2(uint32_t w) {
    __half2 h = *(__half2*)&w;
    return __half22float2(h);
}

__device__ __forceinline__ uint32_t hmax2u(uint32_t a, uint32_t b) {
    uint32_t r;
    asm("max.f16x2 %0, %1, %2;" : "=r"(r) : "r"(a), "r"(b));
    return r;
}

__device__ __forceinline__ uint32_t hadd2u(uint32_t a, uint32_t b) {
    uint32_t r;
    asm("add.rn.f16x2 %0, %1, %2;" : "=r"(r) : "r"(a), "r"(b));
    return r;
}

__device__ __forceinline__ uint32_t hsub2u(uint32_t a, uint32_t b) {
    uint32_t r;
    asm("sub.rn.f16x2 %0, %1, %2;" : "=r"(r) : "r"(a), "r"(b));
    return r;
}

__device__ __forceinline__ uint32_t ex2h2(uint32_t p) {
    uint32_t r;
    asm("ex2.approx.f16x2 %0, %1;" : "=r"(r) : "r"(p));
    return r;
}

__device__ __forceinline__ void cp16(uint32_t dst, const void* src) {
    asm volatile("cp.async.cg.shared.global [%0], [%1], 16;"
                 :: "r"(dst), "l"(__cvta_generic_to_global(src)));
}
#define CP_COMMIT asm volatile("cp.async.commit_group;" ::: "memory")
#define CP_WAIT0  asm volatile("cp.async.wait_group 0;" ::: "memory")

// D += A(16x16 fp16, row) * B(16x8 fp16, col), f32 accumulate
__device__ __forceinline__ void mma16(float d[4], const uint32_t a[4], const uint32_t b[2]) {
    asm volatile(
        "mma.sync.aligned.m16n8k16.row.col.f32.f16.f16.f32 "
        "{%0,%1,%2,%3}, {%4,%5,%6,%7}, {%8,%9}, {%0,%1,%2,%3};"
        : "+f"(d[0]), "+f"(d[1]), "+f"(d[2]), "+f"(d[3])
        : "r"(a[0]), "r"(a[1]), "r"(a[2]), "r"(a[3]), "r"(b[0]), "r"(b[1]));
}

// D += A * B with fp16 accumulate (2 packed regs) — double rate
__device__ __forceinline__ void mma16h(uint32_t d[2], const uint32_t a[4], const uint32_t b[2]) {
    asm volatile(
        "mma.sync.aligned.m16n8k16.row.col.f16.f16.f16.f16 "
        "{%0,%1}, {%2,%3,%4,%5}, {%6,%7}, {%0,%1};"
        : "+r"(d[0]), "+r"(d[1])
        : "r"(a[0]), "r"(a[1]), "r"(a[2]), "r"(a[3]), "r"(b[0]), "r"(b[1]));
}

// ---------------------------------------------------------------------------
// Merged preprocessing (ONE launch)
// ---------------------------------------------------------------------------
__global__ __launch_bounds__(256) void prepro_kernel(
    const float* __restrict__ x, const float* __restrict__ W_qkv,
    const float* __restrict__ W_out,
    uint32_t* __restrict__ x16, __half* __restrict__ wqk,
    __half* __restrict__ wv, __half* __restrict__ wo)
{
    const int id = blockIdx.x;
    const int t = threadIdx.x;

    if (id < 1024) {
        const float4* in = (const float4*)x;
        int i = id * 256 + t;
        float4 v0 = in[i * 4 + 0], v1 = in[i * 4 + 1];
        float4 v2 = in[i * 4 + 2], v3 = in[i * 4 + 3];
        uint32_t* o = x16 + (size_t)i * 8;
        uint4 w;
        w.x = packh2(v0.x, v0.y); w.y = packh2(v2.x, v2.y);
        w.z = packh2(v0.z, v0.w); w.w = packh2(v2.z, v2.w);
        *(uint4*)o = w;
        w.x = packh2(v1.x, v1.y); w.y = packh2(v3.x, v3.y);
        w.z = packh2(v1.z, v1.w); w.w = packh2(v3.z, v3.w);
        *(uint4*)(o + 4) = w;
        return;
    }

    __shared__ float tsh[32][33];
    const int tx = t & 31, ty = t >> 5;
    const float* W; int Nsrc, mode, bx, by;
    if (id < 4096) { int k = id - 1024; bx = k & 31; by = k >> 5; mode = 1; W = W_qkv; Nsrc = EQ_; }
    else           { int k = id - 4096; bx = k & 31; by = k >> 5; mode = 0; W = W_out; Nsrc = D_; }

    const int k0 = bx * 32, r0 = by * 32;
    int col0; float scale = 1.f; __half* dst; int drow;
    if (mode == 0) { col0 = r0; dst = wo; drow = r0; }
    else if (r0 < NQK) {
        col0 = (r0 >> 7) * 192 + (r0 & 127);
        scale = ((r0 & 127) < 64) ? QSCALE : 1.f;
        dst = wqk; drow = r0;
    } else {
        int rv = r0 - NQK;
        col0 = (rv >> 6) * 192 + 128 + (rv & 63);
        dst = wv; drow = rv;
    }
#pragma unroll
    for (int i = 0; i < 32; i += 8)
        tsh[ty + i][tx] = W[(size_t)(k0 + ty + i) * Nsrc + col0 + tx];
    __syncthreads();
#pragma unroll
    for (int it = 0; it < 2; it++) {
        int idx = t + it * 256;
        int ni = idx >> 4, w = idx & 15;
        int g = w >> 3, w8 = w & 7;
        int jl = (w8 & 1) ? (w8 + 7) : w8;
        int j = g * 16 + jl;
        uint32_t p = packh2(tsh[j][ni] * scale, tsh[j + 1][ni] * scale);
        *((uint32_t*)(dst + (size_t)(drow + ni) * D_ + k0) + w) = p;
    }
}

// ---------------------------------------------------------------------------
// fp16 GEMM body (f32 accumulate — K=1024 chains need it)
// ---------------------------------------------------------------------------
#define GSTW 5120   // stage words (128*40)
#define GEMM_SMEM (4 * 20480)

__device__ __forceinline__ float gbias(const float* b, int c, int mode) {
    if (mode == 0) return 0.f;
    if (mode == 1) return b[c];
    float s = ((c & 127) < 64) ? QSCALE : 1.f;
    return b[(c >> 7) * 192 + (c & 127)] * s;
}

template<bool HALF_OUT>
__device__ __forceinline__ void gemm_body(
    const __half* __restrict__ A, const __half* __restrict__ Bw,
    const float* __restrict__ bias, void* __restrict__ C,
    int Nn, int m0, int n0, int bias_mode, char* smem)
{
    const int K = D_;
    const uint32_t sA0 = smem_u32(smem);
    const uint32_t sB0 = sA0 + 2 * 20480;
    const uint32_t* uA = (const uint32_t*)smem;
    const uint32_t* uB = (const uint32_t*)(smem + 2 * 20480);

    const int tid = threadIdx.x;
    const int wid = tid >> 5, lane = tid & 31;
    const int gid = lane >> 2, tig = lane & 3;
    const int wm = wid >> 1, wn = wid & 1;

    float acc[4][8][4];
#pragma unroll
    for (int i = 0; i < 4; i++)
#pragma unroll
        for (int j = 0; j < 8; j++)
#pragma unroll
            for (int r = 0; r < 4; r++) acc[i][j][r] = 0.f;

    auto load_chunk = [&](int k0, int s) {
        const uint32_t da = sA0 + s * 20480;
        const uint32_t db = sB0 + s * 20480;
#pragma unroll
        for (int p = 0; p < 8; p++) {
            int idx = tid + p * 128;
            int m = idx >> 3, c = (idx & 7) * 8;
            cp16(da + (m * 80 + c) * 2, A + (size_t)(m0 + m) * K + k0 + c);
        }
#pragma unroll
        for (int p = 0; p < 8; p++) {
            int idx = tid + p * 128;
            int n = idx >> 3, c = (idx & 7) * 8;
            cp16(db + (n * 80 + c) * 2, Bw + (size_t)(n0 + n) * K + k0 + c);
        }
        CP_COMMIT;
    };

    const int nch = K >> 6;
    load_chunk(0, 0);

    for (int c = 0; c < nch; c++) {
        CP_WAIT0;
        __syncthreads();
        if (c + 1 < nch) load_chunk((c + 1) * 64, (c + 1) & 1);

        const uint32_t* cA = uA + (c & 1) * GSTW;
        const uint32_t* cB = uB + (c & 1) * GSTW;

#pragma unroll
        for (int kk = 0; kk < 4; kk++) {
            const int kw = kk * 8 + 2 * tig;
            uint32_t af[4][4], bf[8][2];
#pragma unroll
            for (int mt = 0; mt < 4; mt++) {
                const uint32_t* pr = cA + (wm * 64 + mt * 16 + gid) * 40 + kw;
                uint2 va = *(const uint2*)pr;
                uint2 vb = *(const uint2*)(pr + 8 * 40);
                af[mt][0] = va.x; af[mt][1] = vb.x;
                af[mt][2] = va.y; af[mt][3] = vb.y;
            }
#pragma unroll
            for (int nt = 0; nt < 8; nt++) {
                uint2 wb = *(const uint2*)(cB + (wn * 64 + nt * 8 + gid) * 40 + kw);
                bf[nt][0] = wb.x; bf[nt][1] = wb.y;
            }
#pragma unroll
            for (int mt = 0; mt < 4; mt++)
#pragma unroll
                for (int nt = 0; nt < 8; nt++)
                    mma16(acc[mt][nt], af[mt], bf[nt]);
        }
    }

    // epilogue
#pragma unroll
    for (int mt = 0; mt < 4; mt++) {
        const int row = m0 + wm * 64 + mt * 16 + gid;
#pragma unroll
        for (int nt = 0; nt < 8; nt++) {
            const int colb = n0 + wn * 64 + nt * 8;
            float bx = gbias(bias, colb + 2 * tig, bias_mode);
            float by = gbias(bias, colb + 2 * tig + 1, bias_mode);
            float v00 = acc[mt][nt][0] + bx, v01 = acc[mt][nt][1] + by;
            float v10 = acc[mt][nt][2] + bx, v11 = acc[mt][nt][3] + by;
            if (HALF_OUT) {
                __half* Ch = (__half*)C;
                size_t off = (size_t)row * Nn + n0 + wn * 64 + 16 * (nt >> 1)
                           + 4 * tig + 2 * (nt & 1);
                *(uint32_t*)(Ch + off) = packh2(v00, v01);
                *(uint32_t*)(Ch + off + (size_t)8 * Nn) = packh2(v10, v11);
            } else {
                float* Cf = (float*)C;
                float2 o0; o0.x = v00; o0.y = v01;
                float2 o1; o1.x = v10; o1.y = v11;
                *(float2*)(Cf + (size_t)row * Nn + colb + 2 * tig) = o0;
                *(float2*)(Cf + (size_t)(row + 8) * Nn + colb + 2 * tig) = o1;
            }
        }
    }
}

// Merged projections: blocks [0,512) = QK proj, [512,768) = V^T.
__global__ __launch_bounds__(128, 2) void proj_kernel(
    const __half* __restrict__ x16, const __half* __restrict__ wqk,
    const __half* __restrict__ wv, const float* __restrict__ b_qkv,
    __half* __restrict__ qkb, __half* __restrict__ vT)
{
    extern __shared__ char smem[];
    const int id = blockIdx.x;
    if (id < 512) {
        int bx = id & 15, by = id >> 4;
        gemm_body<true>(x16, wqk, b_qkv, qkb, NQK, by * 128, bx * 128, 2, smem);
    } else {
        int k = id - 512;
        int bx = k & 31, by = k >> 5;
        gemm_body<true>(wv, x16, nullptr, vT, M_ROWS, by * 128, bx * 128, 0, smem);
    }
}

__global__ __launch_bounds__(128, 2) void outproj_kernel(
    const __half* __restrict__ at16, const __half* __restrict__ wo,
    const float* __restrict__ b_out, float* __restrict__ out)
{
    extern __shared__ char smem[];
    gemm_body<false>(at16, wo, b_out, out, D_,
                     blockIdx.y * 128, blockIdx.x * 128, 1, smem);
}

// ---------------------------------------------------------------------------
// Flash attention: 3 CTAs/SM. QK fp16-acc (double rate). PV ALSO fp16-acc
// per tile (4-mma chain, partials promoted to the f32 master each tile).
// l via HADD2 trees on the fp16 P words (thread-partial, rescaled by scl,
// quad-reduced once at the end). No ones-column.
// smem: Q [128][80hw] | K 2x[64][80] | VT 2x[64][80]  = 61440 B
// ---------------------------------------------------------------------------
#define KSTW 2560            // K/VT stage words (64*40)
#define FLASH_SMEM (20480 + 2*10240 + 2*10240)

__global__ __launch_bounds__(128, 3) void flash_fp16(
    const __half* __restrict__ qk, const __half* __restrict__ vT,
    __half* __restrict__ attn)
{
    extern __shared__ char smem[];
    const uint32_t* Qw = (const uint32_t*)smem;
    const uint32_t* Kw = (const uint32_t*)(smem + 20480);
    const uint32_t* Vw = (const uint32_t*)(smem + 40960);
    const uint32_t sQ = smem_u32(smem);
    const uint32_t sK = sQ + 20480;
    const uint32_t sV = sQ + 40960;

    const int tid = threadIdx.x, wid = tid >> 5, lane = tid & 31;
    const int gid = lane >> 2, tig = lane & 3;
    const int qt = blockIdx.x, h = blockIdx.y, b = blockIdx.z;
    const int q0 = qt * 128;
    const int wr = wid * 32;

    const __half* qbase = qk + (size_t)(b * N_) * NQK + h * 128;

    auto load_kv = [&](int t, int s) {
#pragma unroll
        for (int p = 0; p < 4; p++) {
            int idx = tid + p * 128;
            int r = idx >> 3, c = (idx & 7) * 8;
            cp16(sK + s * 10240 + (r * 80 + c) * 2,
                 qbase + (size_t)(t * 64 + r) * NQK + 64 + c);
            cp16(sV + s * 10240 + (r * 80 + c) * 2,
                 vT + (size_t)(h * 64 + r) * M_ROWS + b * N_ + t * 64 + c);
        }
        CP_COMMIT;
    };

#pragma unroll
    for (int p = 0; p < 8; p++) {
        int idx = tid + p * 128;
        int r = idx >> 3, c = (idx & 7) * 8;
        cp16(sQ + (r * 80 + c) * 2, qbase + (size_t)(q0 + r) * NQK + c);
    }
    load_kv(0, 0);

    float o[2][8][4];
#pragma unroll
    for (int g = 0; g < 2; g++)
#pragma unroll
        for (int nt = 0; nt < 8; nt++)
#pragma unroll
            for (int r = 0; r < 4; r++) o[g][nt][r] = 0.f;
    float mr[2][2] = {{-1e30f, -1e30f}, {-1e30f, -1e30f}};
    float lr[2][2] = {{0.f, 0.f}, {0.f, 0.f}};   // thread-partial row sums

    const int T = N_ / 64;
    for (int t = 0; t < T; t++) {
        CP_WAIT0;
        __syncthreads();
        if (t + 1 < T) load_kv(t + 1, (t + 1) & 1);

        const uint32_t* cK = Kw + (t & 1) * KSTW;
        const uint32_t* cV = Vw + (t & 1) * KSTW;

        // S = Q @ K^T, fp16 accumulators; Q frags reloaded from smem
        uint32_t sc16[2][8][2];
#pragma unroll
        for (int g = 0; g < 2; g++)
#pragma unroll
            for (int nt = 0; nt < 8; nt++) {
                sc16[g][nt][0] = 0u; sc16[g][nt][1] = 0u;
            }
#pragma unroll
        for (int kk = 0; kk < 4; kk++) {
            uint32_t bf[8][2];
#pragma unroll
            for (int nt = 0; nt < 8; nt++) {
                uint2 kb = *(const uint2*)(cK + (nt * 8 + gid) * 40 + kk * 8 + 2 * tig);
                bf[nt][0] = kb.x; bf[nt][1] = kb.y;
            }
#pragma unroll
            for (int g = 0; g < 2; g++) {
                uint32_t af[4];
                const uint32_t* pr = Qw + (wr + g * 16 + gid) * 40 + kk * 8 + 2 * tig;
                uint2 va = *(const uint2*)pr;
                uint2 vb = *(const uint2*)(pr + 8 * 40);
                af[0] = va.x; af[1] = vb.x; af[2] = va.y; af[3] = vb.y;
#pragma unroll
                for (int nt = 0; nt < 8; nt++)
                    mma16h(sc16[g][nt], af, bf[nt]);
            }
        }

        // online softmax on packed halves + thread-partial l via HADD2 trees
#pragma unroll
        for (int g = 0; g < 2; g++) {
            uint32_t ma = sc16[g][0][0], mb = sc16[g][0][1];
#pragma unroll
            for (int nt = 1; nt < 8; nt++) {
                ma = hmax2u(ma, sc16[g][nt][0]);
                mb = hmax2u(mb, sc16[g][nt][1]);
            }
            __half2 ha = *(__half2*)&ma, hb = *(__half2*)&mb;
            float mx0 = fmaxf(__low2float(ha), __high2float(ha));
            float mx1 = fmaxf(__low2float(hb), __high2float(hb));
            mx0 = fmaxf(mx0, __shfl_xor_sync(0xffffffffu, mx0, 1));
            mx0 = fmaxf(mx0, __shfl_xor_sync(0xffffffffu, mx0, 2));
            mx1 = fmaxf(mx1, __shfl_xor_sync(0xffffffffu, mx1, 1));
            mx1 = fmaxf(mx1, __shfl_xor_sync(0xffffffffu, mx1, 2));

            const float mn0 = fmaxf(mr[g][0], mx0), mn1 = fmaxf(mr[g][1], mx1);
            const float scl0 = exp2f(mr[g][0] - mn0), scl1 = exp2f(mr[g][1] - mn1);
            mr[g][0] = mn0; mr[g][1] = mn1;

            const uint32_t mn0h = packh2(mn0, mn0), mn1h = packh2(mn1, mn1);
#pragma unroll
            for (int nt = 0; nt < 8; nt++) {
                sc16[g][nt][0] = ex2h2(hsub2u(sc16[g][nt][0], mn0h));
                sc16[g][nt][1] = ex2h2(hsub2u(sc16[g][nt][1], mn1h));
            }
            // l partial: HADD2 tree over nt (8 words -> 1), then f32 finish
            uint32_t s0 = hadd2u(hadd2u(hadd2u(sc16[g][0][0], sc16[g][1][0]),
                                        hadd2u(sc16[g][2][0], sc16[g][3][0])),
                                 hadd2u(hadd2u(sc16[g][4][0], sc16[g][5][0]),
                                        hadd2u(sc16[g][6][0], sc16[g][7][0])));
            uint32_t s1 = hadd2u(hadd2u(hadd2u(sc16[g][0][1], sc16[g][1][1]),
                                        hadd2u(sc16[g][2][1], sc16[g][3][1])),
                                 hadd2u(hadd2u(sc16[g][4][1], sc16[g][5][1]),
                                        hadd2u(sc16[g][6][1], sc16[g][7][1])));
            float2 f0 = h2f2(s0), f1 = h2f2(s1);
            lr[g][0] = lr[g][0] * scl0 + (f0.x + f0.y);
            lr[g][1] = lr[g][1] * scl1 + (f1.x + f1.y);
            // rescale O master
#pragma unroll
            for (int nt = 0; nt < 8; nt++) {
                o[g][nt][0] *= scl0; o[g][nt][1] *= scl0;
                o[g][nt][2] *= scl1; o[g][nt][3] *= scl1;
            }
        }

        // O += P @ V: fp16-acc per tile (double rate), promote to f32 after
        uint32_t pv[2][8][2];
#pragma unroll
        for (int g = 0; g < 2; g++)
#pragma unroll
            for (int nt = 0; nt < 8; nt++) {
                pv[g][nt][0] = 0u; pv[g][nt][1] = 0u;
            }
#pragma unroll
        for (int kk = 0; kk < 4; kk++) {
            uint32_t vf[8][2];
#pragma unroll
            for (int nt = 0; nt < 8; nt++) {
                uint2 vb = *(const uint2*)(cV + (nt * 8 + gid) * 40 + kk * 8 + 2 * tig);
                vf[nt][0] = vb.x; vf[nt][1] = vb.y;
            }
#pragma unroll
            for (int g = 0; g < 2; g++) {
                uint32_t af[4];
                af[0] = sc16[g][2 * kk][0];
                af[1] = sc16[g][2 * kk][1];
                af[2] = sc16[g][2 * kk + 1][0];
                af[3] = sc16[g][2 * kk + 1][1];
#pragma unroll
                for (int nt = 0; nt < 8; nt++)
                    mma16h(pv[g][nt], af, vf[nt]);
            }
        }
        // promote tile partials into f32 master
#pragma unroll
        for (int g = 0; g < 2; g++)
#pragma unroll
            for (int nt = 0; nt < 8; nt++) {
                float2 plo = h2f2(pv[g][nt][0]);
                float2 phi = h2f2(pv[g][nt][1]);
                o[g][nt][0] += plo.x; o[g][nt][1] += plo.y;
                o[g][nt][2] += phi.x; o[g][nt][3] += phi.y;
            }
    }

    // finalize: quad-reduce thread-partial l, then normalize + store
#pragma unroll
    for (int g = 0; g < 2; g++) {
        float l0 = lr[g][0], l1 = lr[g][1];
        l0 += __shfl_xor_sync(0xffffffffu, l0, 1);
        l0 += __shfl_xor_sync(0xffffffffu, l0, 2);
        l1 += __shfl_xor_sync(0xffffffffu, l1, 1);
        l1 += __shfl_xor_sync(0xffffffffu, l1, 2);
        const float inv0 = 1.0f / l0, inv1 = 1.0f / l1;

        const int q = b * N_ + q0 + wr + g * 16 + gid;
#pragma unroll
        for (int nt = 0; nt < 8; nt++) {
            size_t off = (size_t)q * D_ + h * 64 + 16 * (nt >> 1)
                       + 4 * tig + 2 * (nt & 1);
            *(uint32_t*)(attn + off) = packh2(o[g][nt][0] * inv0, o[g][nt][1] * inv0);
            *(uint32_t*)(attn + off + (size_t)8 * D_) =
                packh2(o[g][nt][2] * inv1, o[g][nt][3] * inv1);
        }
    }
}

// ---------------------------------------------------------------------------
// Launch (4 kernels total)
// ---------------------------------------------------------------------------
extern "C" void kernel_launch(void* const* d_in, const int* in_sizes, int n_in,
                              void* d_out, int out_size)
{
    const float* x     = (const float*)d_in[0];
    const float* W_qkv = (const float*)d_in[1];
    const float* b_qkv = (const float*)d_in[2];
    const float* W_out = (const float*)d_in[3];
    const float* b_out = (const float*)d_in[4];
    float* out = (float*)d_out;

    __half *x16, *wqk, *wv, *wo, *qkb, *vT, *at16;
    cudaGetSymbolAddress((void**)&x16,  g_x16);
    cudaGetSymbolAddress((void**)&wqk,  g_wqk);
    cudaGetSymbolAddress((void**)&wv,   g_wv);
    cudaGetSymbolAddress((void**)&wo,   g_wo);
    cudaGetSymbolAddress((void**)&qkb,  g_qk);
    cudaGetSymbolAddress((void**)&vT,   g_vT);
    cudaGetSymbolAddress((void**)&at16, g_at16);

    cudaFuncSetAttribute((void*)proj_kernel,    cudaFuncAttributeMaxDynamicSharedMemorySize, GEMM_SMEM);
    cudaFuncSetAttribute((void*)outproj_kernel, cudaFuncAttributeMaxDynamicSharedMemorySize, GEMM_SMEM);
    cudaFuncSetAttribute((void*)flash_fp16,     cudaFuncAttributeMaxDynamicSharedMemorySize, FLASH_SMEM);
    cudaFuncSetAttribute((void*)proj_kernel,    cudaFuncAttributePreferredSharedMemoryCarveout, 100);
    cudaFuncSetAttribute((void*)outproj_kernel, cudaFuncAttributePreferredSharedMemoryCarveout, 100);
    cudaFuncSetAttribute((void*)flash_fp16,     cudaFuncAttributePreferredSharedMemoryCarveout, 100);

    // 0) merged preprocessing
    prepro_kernel<<<5120, 256>>>(x, W_qkv, W_out, (uint32_t*)x16, wqk, wv, wo);

    // 1) merged projections: QK (512 CTAs) + V^T (256 CTAs)
    proj_kernel<<<768, 128, GEMM_SMEM>>>(x16, wqk, wv, b_qkv, qkb, vT);

    // 2) fused flash attention -> at16 (3 CTAs/SM, double-rate mma)
    flash_fp16<<<dim3(N_ / 128, H_, B_), 128, FLASH_SMEM>>>(qkb, vT, at16);

    // 3) output projection: f32 out
    outproj_kernel<<<dim3(D_ / 128, M_ROWS / 128), 128, GEMM_SMEM>>>(
        at16, wo, b_out, out);
}